// round 17
// baseline (speedup 1.0000x reference)
#include <cuda_runtime.h>
#include <cstdint>
#include <cstddef>

// LocalConvolution via single-pass TF32 warp MMA (mma.sync m16n8k8).
// R17 = R16 EXACT inner pipeline (2-stage cp.async KT=64, fragment
// double-buffer prefetch, A fed as raw f32 bits) + persistent CTAs with
// atomic position stealing (grid 296 = 2/SM) to remove the 2.65-wave
// quantization tail (~12% of SM-time).
// Per position: D[o=128, b=64] = W[128,K] @ P[64,K]^T, K = 1600.

#define B_  64
#define C_  64
#define H_  32
#define W_  32
#define CC  28
#define O_  128
#define K_  1600
#define KT  64
#define NTILES 25
#define NPOS 784
#define CHW (C_*H_*W_)        // 65536
#define NTH 256
#define GRID 296

// per-stage smem:
//  W f32 [128 rows][68 floats = 272B]
//  P tf32 [64 k-rows][72 floats = 288B]
#define WROWB 272
#define PROWB 288
#define WST_OFF 0                     // 128*272 = 34816
#define PTF_OFF 34816                 // 64*288  = 18432
#define STAGESZ (34816 + 18432)       // 53248
#define SMEM_TOTAL (2*STAGESZ)        // 106496

__device__ uint4 g_xtf[CHW * B_ * 4 / 16];   // tf32 (f32-width) [chw][b]
__device__ int   g_pos_ctr;

__device__ __forceinline__ uint32_t smem_u32(const void* p) {
    uint32_t a;
    asm("{ .reg .u64 t; cvta.to.shared.u64 t, %1; cvt.u32.u64 %0, t; }" : "=r"(a) : "l"(p));
    return a;
}

__device__ __forceinline__ uint32_t f2tf32(float f) {
    uint32_t r;
    asm("cvt.rna.tf32.f32 %0, %1;" : "=r"(r) : "f"(f));
    return r;
}

__device__ __forceinline__ void cp16(uint32_t smem_dst, const void* gmem_src) {
    asm volatile("cp.async.cg.shared.global [%0], [%1], 16;"
                 :: "r"(smem_dst), "l"(__cvta_generic_to_global(gmem_src)) : "memory");
}

__device__ __forceinline__ uint32_t lds32u(uint32_t addr) {
    uint32_t v;
    asm volatile("ld.shared.u32 %0, [%1];" : "=r"(v) : "r"(addr));
    return v;
}

__device__ __forceinline__ void mma_tf32(float* d, const uint32_t* a, uint32_t b0, uint32_t b1) {
    asm volatile(
        "mma.sync.aligned.m16n8k8.row.col.f32.tf32.tf32.f32 "
        "{%0,%1,%2,%3}, {%4,%5,%6,%7}, {%8,%9}, {%0,%1,%2,%3};"
        : "+f"(d[0]), "+f"(d[1]), "+f"(d[2]), "+f"(d[3])
        : "r"(a[0]), "r"(a[1]), "r"(a[2]), "r"(a[3]), "r"(b0), "r"(b1));
}

// ---- prep: x[b][chw] f32 -> g_xtf [chw][b] tf32; resets the work counter ----
__global__ __launch_bounds__(256)
void prep_kernel(const float* __restrict__ x) {
    __shared__ float ts[B_][65];
    const int tid = threadIdx.x;
    const int wid = tid >> 5;
    const int lane = tid & 31;
    const int chw0 = blockIdx.x * 64;

    if (blockIdx.x == 0 && tid == 0) g_pos_ctr = 0;

    #pragma unroll
    for (int bi = 0; bi < 8; bi++) {
        int b = wid * 8 + bi;
        const float* xp = x + (size_t)b * CHW + chw0;
        ts[b][lane]      = xp[lane];
        ts[b][lane + 32] = xp[lane + 32];
    }
    __syncthreads();

    const int chw_l = tid >> 2;
    const int bc = tid & 3;
    uint32_t v[16];
    #pragma unroll
    for (int p = 0; p < 16; p++)
        v[p] = f2tf32(ts[bc * 16 + p][chw_l]);
    char* op = (char*)g_xtf + (size_t)(chw0 + chw_l) * 256 + bc * 64;
    *(uint4*)(op)      = make_uint4(v[0],  v[1],  v[2],  v[3]);
    *(uint4*)(op + 16) = make_uint4(v[4],  v[5],  v[6],  v[7]);
    *(uint4*)(op + 32) = make_uint4(v[8],  v[9],  v[10], v[11]);
    *(uint4*)(op + 48) = make_uint4(v[12], v[13], v[14], v[15]);
}

// ---- main kernel: persistent, 256 threads, 8 warps of 32o x 32b ----
__global__ __launch_bounds__(NTH, 2)
void lc_hmma_kernel(const float* __restrict__ x,
                    const float* __restrict__ w,
                    float* __restrict__ out) {
    extern __shared__ char smem[];
    const uint32_t sbase = smem_u32(smem);

    const int tid = threadIdx.x;
    const int wid = tid >> 5;
    const int l   = tid & 31;

    const int o0 = (wid >> 1) * 32;
    const int b0 = (wid & 1) * 32;
    const int c4 = l & 3;
    const int r8 = l >> 2;

    __shared__ int s_pos;

    // A lane base (relative): row = o0 + r8, col(float) = c4
    const uint32_t aBaseRel = (uint32_t)(WST_OFF + (o0 + r8) * WROWB + c4 * 4);
    // B lane base (relative): k-row = c4, n = b0 + r8
    const uint32_t bBaseRel = (uint32_t)(PTF_OFF + c4 * PROWB + (b0 + r8) * 4);

    while (true) {
        if (tid == 0) s_pos = atomicAdd(&g_pos_ctr, 1);
        __syncthreads();
        const int pos = s_pos;
        if (pos >= NPOS) break;

        const int i = pos / CC;
        const int j = pos - i * CC;
        const float* __restrict__ wbase = w + (size_t)pos * (O_ * K_);

        // ---- cp.async stage fill for tile t into stage s ----
        auto stage_fill = [&](int t, int s) {
            const uint32_t stOff = sbase + (uint32_t)s * STAGESZ;
            const float* wt = wbase + t * KT;
            // W: 128 rows x 64 f32 = 2048 granules, 8 per thread
            #pragma unroll
            for (int ci = 0; ci < 8; ci++) {
                int idx = tid + ci * NTH;
                int row = idx >> 4;
                int g16 = idx & 15;
                cp16(stOff + WST_OFF + row * WROWB + g16 * 16,
                     wt + (size_t)row * K_ + g16 * 4);
            }
            // P: 64 k-rows x 256B = 1024 granules, 4 per thread
            #pragma unroll
            for (int ci = 0; ci < 4; ci++) {
                int idx = tid + ci * NTH;
                int row = idx >> 4;
                int g16 = idx & 15;
                int kg = t * KT + row;
                int c = kg / 25;
                int rem = kg - c * 25;
                int u = rem / 5;
                int v = rem - u * 5;
                size_t sp = ((size_t)(c * (H_ * W_) + (i + u) * W_ + (j + v))) * 256 + g16 * 16;
                cp16(stOff + PTF_OFF + row * PROWB + g16 * 16, (const char*)g_xtf + sp);
            }
            asm volatile("cp.async.commit_group;" ::: "memory");
        };

        float acc[2][4][4];
        #pragma unroll
        for (int mi = 0; mi < 2; mi++)
            #pragma unroll
            for (int bt = 0; bt < 4; bt++)
                #pragma unroll
                for (int c = 0; c < 4; c++) acc[mi][bt][c] = 0.0f;

        stage_fill(0, 0);
        stage_fill(1, 1);

        #pragma unroll 1
        for (int t = 0; t < NTILES; t++) {
            if (t == NTILES - 1) {
                asm volatile("cp.async.wait_group 0;" ::: "memory");
            } else {
                asm volatile("cp.async.wait_group 1;" ::: "memory");
            }
            __syncthreads();

            const uint32_t stOff = sbase + (uint32_t)(t & 1) * STAGESZ;
            const uint32_t aBase = stOff + aBaseRel;
            const uint32_t bBase = stOff + bBaseRel;

            // fragment loader for k8-step ks (A raw f32 bits; B pre-tf32)
            auto load_frags = [&](int ks, uint32_t a[2][4], uint32_t b[4][2]) {
                const uint32_t aCol = (uint32_t)(ks * 32);
                #pragma unroll
                for (int mi = 0; mi < 2; mi++) {
                    const uint32_t rb0 = aBase + (uint32_t)(mi * 16) * WROWB + aCol;
                    const uint32_t rb1 = rb0 + 8 * WROWB;
                    a[mi][0] = lds32u(rb0);
                    a[mi][1] = lds32u(rb1);
                    a[mi][2] = lds32u(rb0 + 16);
                    a[mi][3] = lds32u(rb1 + 16);
                }
                const uint32_t bk = bBase + (uint32_t)(ks * 8) * PROWB;
                #pragma unroll
                for (int bt = 0; bt < 4; bt++) {
                    b[bt][0] = lds32u(bk + bt * 32);
                    b[bt][1] = lds32u(bk + 4 * PROWB + bt * 32);
                }
            };

            uint32_t afr[2][2][4], bfr[2][4][2];
            load_frags(0, afr[0], bfr[0]);
            #pragma unroll
            for (int ks = 0; ks < 8; ks++) {
                const int cur = ks & 1;
                if (ks < 7) load_frags(ks + 1, afr[cur ^ 1], bfr[cur ^ 1]);
                #pragma unroll
                for (int mi = 0; mi < 2; mi++)
                    #pragma unroll
                    for (int bt = 0; bt < 4; bt++)
                        mma_tf32(acc[mi][bt], afr[cur][mi], bfr[cur][bt][0], bfr[cur][bt][1]);
            }
            __syncthreads();

            if (t + 2 < NTILES) stage_fill(t + 2, t & 1);
        }

        // ---- epilogue: o = o0+mi*16+r8+8*(c>>1), b = b0+bt*8+c4*2+(c&1)
        #pragma unroll
        for (int mi = 0; mi < 2; mi++) {
            #pragma unroll
            for (int bt = 0; bt < 4; bt++) {
                #pragma unroll
                for (int c = 0; c < 4; c++) {
                    int o = o0 + mi * 16 + r8 + (c >> 1) * 8;
                    int b = b0 + bt * 8 + c4 * 2 + (c & 1);
                    out[((size_t)b * O_ + o) * NPOS + pos] = acc[mi][bt][c];
                }
            }
        }
        // keep warps from refilling stages for the next position while others
        // still read the last tiles of this one
        __syncthreads();
    }
}

extern "C" void kernel_launch(void* const* d_in, const int* in_sizes, int n_in,
                              void* d_out, int out_size) {
    const float* x;
    const float* w;
    if (in_sizes[0] == B_ * C_ * H_ * W_) {
        x = (const float*)d_in[0];
        w = (const float*)d_in[1];
    } else {
        x = (const float*)d_in[1];
        w = (const float*)d_in[0];
    }
    float* out = (float*)d_out;
    prep_kernel<<<CHW / 64, 256>>>(x);
    cudaFuncSetAttribute(lc_hmma_kernel, cudaFuncAttributeMaxDynamicSharedMemorySize, SMEM_TOTAL);
    lc_hmma_kernel<<<GRID, NTH, SMEM_TOTAL>>>(x, w, out);
}